// round 8
// baseline (speedup 1.0000x reference)
#include <cuda_runtime.h>
#include <cuda_bf16.h>

// B = 8192 rows, T = 4096 features, G = 64 groups.
// Group sizes cycle (32, 64, 96, 64) x 16; all boundaries are multiples of 32,
// so each aligned 32-elem chunk belongs to exactly one group (128 chunks/row).
// Output: d_out[0..B) = Z (fp32), d_out[B..B+B*64) = a (fp32 row-major [B,64]).
//
// R8: two-kernel split to make the 128MB stream BARRIER-FREE.
//  k1: R1's load+butterfly body, chunk sums go straight to gmem scratch.
//      No smem, no __syncthreads, no epilogue -> pure streaming reduce.
//  k2: tiny (6MB traffic): warp per row, load 128 chunk sums, R6 epilogue.

#define T_DIM    4096
#define G_DIM    64
#define B_DIM    8192
#define NTHREADS 256

__device__ float g_chunks[B_DIM * 128];   // 4MB static scratch

// ---------------- kernel 1: stream + chunk reduce ----------------
__global__ __launch_bounds__(NTHREADS, 8)
void agp_stream(const float* __restrict__ H)
{
    const int b   = blockIdx.x;
    const int tid = threadIdx.x;

    const float4* row4 = reinterpret_cast<const float4*>(H + (size_t)b * T_DIM);
    float* dst = g_chunks + (size_t)b * 128;

    #pragma unroll
    for (int k = 0; k < 4; ++k) {
        float4 v = row4[tid + NTHREADS * k];
        float s = (v.x + v.y) + (v.z + v.w);
        // aligned 8-lane butterfly -> 32-elem chunk sum in lanes 0,8,16,24
        s += __shfl_xor_sync(0xffffffffu, s, 1);
        s += __shfl_xor_sync(0xffffffffu, s, 2);
        s += __shfl_xor_sync(0xffffffffu, s, 4);
        if ((tid & 7) == 0)
            dst[(tid >> 3) + 32 * k] = s;
    }
}

// ---------------- kernel 2: chunks -> groups -> softmax -> Z ----------------
__global__ __launch_bounds__(NTHREADS, 8)
void agp_epilogue(const float* __restrict__ score_w,
                  const float* __restrict__ score_b,
                  float* __restrict__ out, int B)
{
    const int tid  = threadIdx.x;
    const int wid  = tid >> 5;
    const int lane = tid & 31;
    const int b    = blockIdx.x * 8 + wid;   // one warp per row

    __shared__ float cs[8][128];

    // coalesced: lane loads chunks 4*lane .. 4*lane+3
    const float4* src = reinterpret_cast<const float4*>(g_chunks + (size_t)b * 128);
    float4 c4 = src[lane];
    *reinterpret_cast<float4*>(&cs[wid][lane * 4]) = c4;
    __syncwarp();

    const float w    = __ldg(score_w);
    const float bias = __ldg(score_b);

    // per-subgroup (g & 3): chunk start within 8-chunk cycle, count, 1/size
    const int   c_start[4] = {0, 1, 3, 6};
    const int   c_cnt[4]   = {1, 2, 3, 2};
    const float inv_sz[4]  = {1.0f/32.0f, 1.0f/64.0f, 1.0f/96.0f, 1.0f/64.0f};

    float Gm[2], sc[2];
    #pragma unroll
    for (int j = 0; j < 2; ++j) {
        int g    = lane + 32 * j;
        int sub  = g & 3;
        int base = (g >> 2) * 8 + c_start[sub];
        float s = 0.0f;
        #pragma unroll
        for (int c = 0; c < 3; ++c)
            if (c < c_cnt[sub]) s += cs[wid][base + c];
        Gm[j] = s * inv_sz[sub];
        sc[j] = Gm[j] * w + bias;
    }

    // max tree (required before exp)
    float mx = fmaxf(sc[0], sc[1]);
    #pragma unroll
    for (int d = 16; d > 0; d >>= 1)
        mx = fmaxf(mx, __shfl_xor_sync(0xffffffffu, mx, d));

    float p0 = __expf(sc[0] - mx);
    float p1 = __expf(sc[1] - mx);

    // interleaved independent trees: ssum = sum(p), pz = sum(p*G)
    float ssum = p0 + p1;
    float pz   = p0 * Gm[0] + p1 * Gm[1];
    #pragma unroll
    for (int d = 16; d > 0; d >>= 1) {
        ssum += __shfl_xor_sync(0xffffffffu, ssum, d);
        pz   += __shfl_xor_sync(0xffffffffu, pz, d);
    }
    float inv = 1.0f / ssum;

    float* a_out = out + B + (size_t)b * G_DIM;
    a_out[lane]      = p0 * inv;
    a_out[lane + 32] = p1 * inv;
    if (lane == 0) out[b] = pz * inv;   // Z = sum(a*G) = pz / ssum
}

extern "C" void kernel_launch(void* const* d_in, const int* in_sizes, int n_in,
                              void* d_out, int out_size)
{
    const float* H  = (const float*)d_in[0];   // [B, 4096]
    const float* sw = (const float*)d_in[1];   // [1,1]
    const float* sb = (const float*)d_in[2];   // [1]
    float* out = (float*)d_out;

    int B = in_sizes[0] / T_DIM;               // 8192
    agp_stream<<<B, NTHREADS>>>(H);
    agp_epilogue<<<B / 8, NTHREADS>>>(sw, sb, out, B);
}

// round 9
// speedup vs baseline: 1.0491x; 1.0491x over previous
#include <cuda_runtime.h>
#include <cuda_bf16.h>

// B = 8192 rows, T = 4096 features, G = 64 groups.
// Group sizes cycle (32, 64, 96, 64) x 16; all boundaries are multiples of 32,
// so each aligned 32-elem chunk belongs to exactly one group (128 chunks/row).
// Output: d_out[0..B) = Z (fp32), d_out[B..B+B*64) = a (fp32 row-major [B,64]).
//
// R9: WARP = ROW. One warp streams its whole row (32 x coalesced float4/lane,
// batched 4-deep like R1), butterfly-reduces to chunk sums in a warp-private
// smem slice (__syncwarp only, NO __syncthreads), then does its own group
// sums + softmax + writes. Zero inter-warp coupling: no barrier drains, no
// CTA-slot idle during epilogues — other warps keep the load pipe full.
// Single kernel, no scratch round-trip (vs R8).

#define T_DIM    4096
#define G_DIM    64
#define NTHREADS 256
#define WARPS    (NTHREADS / 32)

__global__ __launch_bounds__(NTHREADS, 8)
void agp_kernel(const float* __restrict__ H,
                const float* __restrict__ score_w,
                const float* __restrict__ score_b,
                float* __restrict__ out, int B)
{
    const int tid  = threadIdx.x;
    const int wid  = tid >> 5;
    const int lane = tid & 31;
    const int b    = blockIdx.x * WARPS + wid;   // one warp per row

    __shared__ float cs[WARPS][128];             // warp-private chunk sums

    const float4* row4 = reinterpret_cast<const float4*>(H + (size_t)b * T_DIM);

    // ---- stream the row: 8 batches of 4 independent LDG.128 per lane ----
    #pragma unroll 1
    for (int o = 0; o < 8; ++o) {
        float4 v[4];
        #pragma unroll
        for (int j = 0; j < 4; ++j)
            v[j] = row4[(o * 4 + j) * 32 + lane];
        #pragma unroll
        for (int j = 0; j < 4; ++j) {
            float s = (v[j].x + v[j].y) + (v[j].z + v[j].w);
            // aligned 8-lane butterfly -> one 32-elem chunk sum
            s += __shfl_xor_sync(0xffffffffu, s, 1);
            s += __shfl_xor_sync(0xffffffffu, s, 2);
            s += __shfl_xor_sync(0xffffffffu, s, 4);
            if ((lane & 7) == 0)
                cs[wid][(lane >> 3) + 4 * (o * 4 + j)] = s;
        }
    }
    __syncwarp();

    // ---- warp-local epilogue: lane l owns groups 2l and 2l+1 ----
    const float w    = __ldg(score_w);
    const float bias = __ldg(score_b);

    // per-subgroup (g & 3): chunk start within 8-chunk cycle, count, 1/size
    const int   c_start[4] = {0, 1, 3, 6};
    const int   c_cnt[4]   = {1, 2, 3, 2};
    const float inv_sz[4]  = {1.0f/32.0f, 1.0f/64.0f, 1.0f/96.0f, 1.0f/64.0f};

    float Gm[2], sc[2];
    #pragma unroll
    for (int j = 0; j < 2; ++j) {
        int g    = 2 * lane + j;
        int sub  = g & 3;
        int base = (g >> 2) * 8 + c_start[sub];
        float s = 0.0f;
        #pragma unroll
        for (int c = 0; c < 3; ++c)
            if (c < c_cnt[sub]) s += cs[wid][base + c];
        Gm[j] = s * inv_sz[sub];
        sc[j] = Gm[j] * w + bias;
    }

    // max tree (required before exp)
    float mx = fmaxf(sc[0], sc[1]);
    #pragma unroll
    for (int d = 16; d > 0; d >>= 1)
        mx = fmaxf(mx, __shfl_xor_sync(0xffffffffu, mx, d));

    float p0 = __expf(sc[0] - mx);
    float p1 = __expf(sc[1] - mx);

    // interleaved independent trees: ssum = sum(p), pz = sum(p*G)
    float ssum = p0 + p1;
    float pz   = p0 * Gm[0] + p1 * Gm[1];
    #pragma unroll
    for (int d = 16; d > 0; d >>= 1) {
        ssum += __shfl_xor_sync(0xffffffffu, ssum, d);
        pz   += __shfl_xor_sync(0xffffffffu, pz, d);
    }
    float inv = 1.0f / ssum;

    // a: 64 contiguous floats per row, float2 per lane -> coalesced
    float2 ar = make_float2(p0 * inv, p1 * inv);
    *reinterpret_cast<float2*>(out + B + (size_t)b * G_DIM + 2 * lane) = ar;
    if (lane == 0) out[b] = pz * inv;   // Z = sum(a*G) = pz / ssum
}

extern "C" void kernel_launch(void* const* d_in, const int* in_sizes, int n_in,
                              void* d_out, int out_size)
{
    const float* H  = (const float*)d_in[0];   // [B, 4096]
    const float* sw = (const float*)d_in[1];   // [1,1]
    const float* sb = (const float*)d_in[2];   // [1]
    float* out = (float*)d_out;

    int B = in_sizes[0] / T_DIM;               // 8192
    agp_kernel<<<B / WARPS, NTHREADS>>>(H, sw, sb, out, B);
}